// round 17
// baseline (speedup 1.0000x reference)
#include <cuda_runtime.h>
#include <cuda_bf16.h>
#include <math.h>
#include <stdint.h>

#define NN      100000
#define NE      2000000
#define HH      64
#define TPB     256
#define ETPB    512
#define EPT     256     // edges per tile

typedef unsigned long long ull;

// ---------------- device scratch ----------------
__device__ __align__(16) float g_h[NN * HH];
__device__ __align__(16) uint16_t g_hb[NN * HH];   // bf16 mirror of g_h
__device__ __align__(16) float g_agg[NN * HH];     // invariant: zero on entry to each edge phase
__device__ int g_src[NE + 512];
__device__ int g_dst[NE + 512];
__device__ int g_cnt1;
__device__ int g_blkdone;
__device__ int g_cur0, g_cur1;
__device__ int g_b0p, g_ntiles;

__device__ __forceinline__ float sigf(float v) { return 1.f / (1.f + __expf(-v)); }

__device__ __forceinline__ void red_add_v4(float* p, float a, float b, float c, float d) {
    asm volatile("red.global.add.v4.f32 [%0], {%1, %2, %3, %4};"
                 :: "l"(p), "f"(a), "f"(b), "f"(c), "f"(d) : "memory");
}

// bf16 helpers
__device__ __forceinline__ uint32_t bf2(float lo, float hi) {
    uint32_t r;
    asm("cvt.rn.bf16x2.f32 %0, %1, %2;" : "=r"(r) : "f"(hi), "f"(lo));
    return r;
}
__device__ __forceinline__ void mma_bf16(float* c, uint32_t a0, uint32_t a1,
                                         uint32_t a2, uint32_t a3,
                                         uint32_t b0, uint32_t b1) {
    asm volatile("mma.sync.aligned.m16n8k16.row.col.f32.bf16.bf16.f32 "
                 "{%0,%1,%2,%3}, {%4,%5,%6,%7}, {%8,%9}, {%0,%1,%2,%3};"
                 : "+f"(c[0]), "+f"(c[1]), "+f"(c[2]), "+f"(c[3])
                 : "r"(a0), "r"(a1), "r"(a2), "r"(a3), "r"(b0), "r"(b1));
}
__device__ __forceinline__ void ldsm4(uint32_t& r0, uint32_t& r1, uint32_t& r2,
                                      uint32_t& r3, uint32_t addr) {
    asm volatile("ldmatrix.sync.aligned.m8n8.x4.shared.b16 {%0,%1,%2,%3}, [%4];"
                 : "=r"(r0), "=r"(r1), "=r"(r2), "=r"(r3) : "r"(addr));
}
__device__ __forceinline__ uint32_t smem_u32(const void* p) {
    uint32_t a;
    asm("{ .reg .u64 t; cvta.to.shared.u64 t, %1; cvt.u32.u64 %0, t; }" : "=r"(a) : "l"(p));
    return a;
}

// ---------------- fused edge count + scan (last-block pattern, 256-aligned) ----------------
__global__ __launch_bounds__(TPB) void tg_countscan(const int* __restrict__ et) {
    __shared__ int sm[8];
    int tid = threadIdx.x;
    int s = 0;
    for (int e = blockIdx.x*TPB + tid; e < NE; e += gridDim.x*TPB) s += et[e];
    #pragma unroll
    for (int o = 16; o; o >>= 1) s += __shfl_xor_sync(0xffffffffu, s, o);
    if ((tid & 31) == 0) sm[tid >> 5] = s;
    __syncthreads();
    if (tid == 0) {
        int t = 0; for (int j = 0; j < 8; j++) t += sm[j];
        atomicAdd(&g_cnt1, t);
        __threadfence();
        int done = atomicAdd(&g_blkdone, 1);
        if (done == (int)gridDim.x - 1) {
            int c1 = atomicAdd(&g_cnt1, 0);
            g_cnt1 = 0; g_blkdone = 0;
            int c0 = NE - c1;
            int b0p = (c0 + 255) & ~255;
            int end1 = b0p + c1;
            int nt = (end1 + 255) >> 8;
            g_b0p = b0p; g_ntiles = nt;
            g_cur0 = 0; g_cur1 = b0p;
            for (int i = c0; i < b0p; i++)      { g_src[i] = 0; g_dst[i] = NN; }
            for (int i = end1; i < nt*256; i++) { g_src[i] = 0; g_dst[i] = NN; }
        }
    }
}

__global__ __launch_bounds__(TPB) void tg_scatter(const int* __restrict__ et,
                                                  const int* __restrict__ ei) {
    int lane = threadIdx.x & 31;
    unsigned lt = (1u << lane) - 1u;
    for (int e = blockIdx.x*TPB + threadIdx.x; e < NE; e += gridDim.x*TPB) {
        int t = et[e];
        unsigned m1 = __ballot_sync(0xffffffffu, t);
        int n1 = __popc(m1);
        int b0 = 0, b1 = 0;
        if (lane == 0) {
            b0 = atomicAdd(&g_cur0, 32 - n1);
            b1 = atomicAdd(&g_cur1, n1);
        }
        b0 = __shfl_sync(0xffffffffu, b0, 0);
        b1 = __shfl_sync(0xffffffffu, b1, 0);
        int pos = t ? (b1 + __popc(m1 & lt)) : (b0 + __popc(~m1 & lt));
        g_src[pos] = ei[e];
        g_dst[pos] = ei[NE + e];
    }
}

// ---------------- input projection: h = relu(LN(x@W+b)); writes g_h and g_hb ----------------
__global__ __launch_bounds__(TPB) void tg_input(const float* __restrict__ x,
    const float* __restrict__ in_w, const float* __restrict__ in_b,
    const float* __restrict__ ln_g, const float* __restrict__ ln_b)
{
    __shared__ float sw[256], sb[64], sg[64], sbn[64];
    int tid = threadIdx.x;
    if (tid < 256) sw[tid] = in_w[tid];
    if (tid < 64) { sb[tid] = in_b[tid]; sg[tid] = ln_g[tid]; sbn[tid] = ln_b[tid]; }
    __syncthreads();
    int lane = tid & 31;
    int warpsTotal = gridDim.x * (TPB / 32);
    for (int node = blockIdx.x * (TPB/32) + (tid >> 5); node < NN; node += warpsTotal) {
        float4 xv = *(const float4*)(x + node * 4);
        int c0 = lane * 2;
        float v0 = sb[c0]   + xv.x*sw[c0]   + xv.y*sw[64+c0]   + xv.z*sw[128+c0]   + xv.w*sw[192+c0];
        float v1 = sb[c0+1] + xv.x*sw[c0+1] + xv.y*sw[64+c0+1] + xv.z*sw[128+c0+1] + xv.w*sw[192+c0+1];
        float s = v0 + v1;
        #pragma unroll
        for (int o = 16; o; o >>= 1) s += __shfl_xor_sync(0xffffffffu, s, o);
        float mu = s * (1.0f/64.0f);
        float d0 = v0 - mu, d1 = v1 - mu;
        float q = d0*d0 + d1*d1;
        #pragma unroll
        for (int o = 16; o; o >>= 1) q += __shfl_xor_sync(0xffffffffu, q, o);
        float inv = rsqrtf(q * (1.0f/64.0f) + 1e-5f);
        float h0 = fmaxf(d0*inv*sg[c0]   + sbn[c0],   0.f);
        float h1 = fmaxf(d1*inv*sg[c0+1] + sbn[c0+1], 0.f);
        g_h[node*64 + c0]   = h0;
        g_h[node*64 + c0+1] = h1;
        *(uint32_t*)(g_hb + (size_t)node*64 + c0) = bf2(h0, h1);
    }
}

// ---------------- persistent edge MLP: 256-edge tiles, warp = 32e x 32c, bf16 gather ----------------
// byte layout:
//  smi  [256e][136 bf16] @0        (69632 B)  row pitch 272 B
//  sh1  [256e][72 bf16]  @69632    (36864 B)  row pitch 144 B
//  sW1F fragment-major   @106496   (32768 B)
//  sW2F fragment-major   @139264   (16384 B)
//  sb1 f32 @155648 (512) | sb2 f32 @156160 (512) -> total 156672 B
#define OFFE_H1  69632
#define OFFE_W1F 106496
#define OFFE_W2F 139264
#define OFFE_B1  155648
#define OFFE_B2  156160
#define EDGE_SMEM 156672

__global__ __launch_bounds__(ETPB, 1) void tg_edge(const float* __restrict__ w1g,
    const float* __restrict__ b1g, const float* __restrict__ w2g, const float* __restrict__ b2g)
{
    extern __shared__ char smraw[];
    uint32_t* sW1F   = (uint32_t*)(smraw + OFFE_W1F);
    uint32_t* sW2F   = (uint32_t*)(smraw + OFFE_W2F);
    float*    sb1    = (float*)(smraw + OFFE_B1);
    float*    sb2    = (float*)(smraw + OFFE_B2);

    int tid = threadIdx.x;
    int lane = tid & 31;
    int warp = tid >> 5;          // 0..15
    int eg   = warp & 7;          // edge group: rows [32eg, 32eg+32)
    int ch   = warp >> 3;         // col half: cols [32ch, 32ch+32)
    int grp  = lane >> 2;         // 0..7
    int tig  = lane & 3;          // 0..3
    int erow = eg*32 + grp;       // fragment rows erow(+8), erow+16(+8)

    // stage fragment-major bf16 weights once
    for (int i = tid; i < 8192; i += ETPB) {
        int w = i & 1, ln = (i >> 1) & 31, kb = (i >> 6) & 7, nc = (i >> 9) & 7, ty = i >> 12;
        int g = ln >> 2, tg = ln & 3;
        int k = kb*16 + 2*tg + 8*w;
        int c = nc*8 + g;
        const float* wp = w1g + ty*8192 + k*64 + c;
        sW1F[i] = bf2(wp[0], wp[64]);
    }
    for (int i = tid; i < 4096; i += ETPB) {
        int w = i & 1, ln = (i >> 1) & 31, kb = (i >> 6) & 3, nc = (i >> 8) & 7, ty = i >> 11;
        int g = ln >> 2, tg = ln & 3;
        int k = kb*16 + 2*tg + 8*w;
        int c = nc*8 + g;
        const float* wp = w2g + ty*4096 + k*64 + c;
        sW2F[i] = bf2(wp[0], wp[64]);
    }
    if (tid < 128) { sb1[tid] = b1g[tid]; sb2[tid] = b2g[tid]; }

    uint32_t smi_s = smem_u32(smraw);
    uint32_t aAddr1 = smi_s + (eg*32 + (lane & 15))*272 + (lane >> 4)*16;
    uint32_t aAddr2 = smi_s + OFFE_H1 + (eg*32 + (lane & 15))*144 + (lane >> 4)*16;

    int ntiles = g_ntiles, b0p = g_b0p;

    for (int tile = blockIdx.x; tile < ntiles; tile += gridDim.x) {
        int base = tile * EPT;
        int t = (base >= b0p) ? 1 : 0;

        __syncthreads();  // previous tile fully consumed before overwriting smi
        // gather mi = [hb[src] | hb[dst]] (bf16 source, no convert): 256 rows x 32 uint2
        for (int i = tid; i < 8192; i += ETPB) {
            int ee = i >> 5, c = i & 31;
            int idx = (c < 16) ? g_src[base + ee] : g_dst[base + ee];
            if (idx >= NN) idx = 0;
            uint2 u = *(const uint2*)(g_hb + (size_t)idx*64 + (c & 15)*4);
            *(uint2*)(smraw + ee*272 + c*8) = u;
        }
        __syncthreads();

        // ---- stage 1: D[256e][64c] = mi @ W1  (k=128, 8 k16 blocks, 2 A-frags/warp) ----
        float acc[2][4][4];
        #pragma unroll
        for (int f = 0; f < 2; f++)
            #pragma unroll
            for (int n = 0; n < 4; n++) { acc[f][n][0]=0.f; acc[f][n][1]=0.f; acc[f][n][2]=0.f; acc[f][n][3]=0.f; }
        {
            const uint32_t* wF = sW1F + (t*8 + ch*4)*8*64;
            #pragma unroll
            for (int kb = 0; kb < 8; kb++) {
                uint32_t a0, a1, a2, a3, c0r, c1r, c2r, c3r;
                ldsm4(a0, a1, a2, a3, aAddr1 + kb*32);
                ldsm4(c0r, c1r, c2r, c3r, aAddr1 + 16*272 + kb*32);
                #pragma unroll
                for (int n = 0; n < 4; n++) {
                    uint2 bv = *(const uint2*)(wF + (n*8 + kb)*64 + 2*lane);
                    mma_bf16(acc[0][n], a0, a1, a2, a3, bv.x, bv.y);
                    mma_bf16(acc[1][n], c0r, c1r, c2r, c3r, bv.x, bv.y);
                }
            }
        }
        // epilogue 1: bias + relu -> bf16 -> sh1
        {
            const float* bb = sb1 + t*64;
            #pragma unroll
            for (int f = 0; f < 2; f++)
                #pragma unroll
                for (int n = 0; n < 4; n++) {
                    int c = ch*32 + n*8 + 2*tig;
                    float2 b = *(const float2*)(bb + c);
                    uint32_t lo = bf2(fmaxf(acc[f][n][0] + b.x, 0.f), fmaxf(acc[f][n][1] + b.y, 0.f));
                    uint32_t hi = bf2(fmaxf(acc[f][n][2] + b.x, 0.f), fmaxf(acc[f][n][3] + b.y, 0.f));
                    *(uint32_t*)(smraw + OFFE_H1 + (erow + f*16)*144 + c*2)     = lo;
                    *(uint32_t*)(smraw + OFFE_H1 + (erow + f*16 + 8)*144 + c*2) = hi;
                }
        }
        __syncthreads();

        // ---- stage 2: msg = h1 @ W2  (k=64, 4 k16 blocks, 2 A-frags/warp) ----
        #pragma unroll
        for (int f = 0; f < 2; f++)
            #pragma unroll
            for (int n = 0; n < 4; n++) { acc[f][n][0]=0.f; acc[f][n][1]=0.f; acc[f][n][2]=0.f; acc[f][n][3]=0.f; }
        {
            const uint32_t* wF = sW2F + (t*8 + ch*4)*4*64;
            #pragma unroll
            for (int kb = 0; kb < 4; kb++) {
                uint32_t a0, a1, a2, a3, c0r, c1r, c2r, c3r;
                ldsm4(a0, a1, a2, a3, aAddr2 + kb*32);
                ldsm4(c0r, c1r, c2r, c3r, aAddr2 + 16*144 + kb*32);
                #pragma unroll
                for (int n = 0; n < 4; n++) {
                    uint2 bv = *(const uint2*)(wF + (n*4 + kb)*64 + 2*lane);
                    mma_bf16(acc[0][n], a0, a1, a2, a3, bv.x, bv.y);
                    mma_bf16(acc[1][n], c0r, c1r, c2r, c3r, bv.x, bv.y);
                }
            }
        }
        // epilogue 2: bias + tig-parity butterfly -> red.v4 scatter
        {
            const float* bb = sb2 + t*64;
            #pragma unroll
            for (int f = 0; f < 2; f++) {
                int dA = g_dst[base + erow + f*16];
                int dB = g_dst[base + erow + f*16 + 8];
                #pragma unroll
                for (int n = 0; n < 4; n++) {
                    int c = ch*32 + n*8 + 2*tig;
                    float2 b = *(const float2*)(bb + c);
                    float v0 = acc[f][n][0] + b.x, v1 = acc[f][n][1] + b.y;
                    float v2 = acc[f][n][2] + b.x, v3 = acc[f][n][3] + b.y;
                    float r0 = __shfl_xor_sync(0xffffffffu, v0, 1);
                    float r1 = __shfl_xor_sync(0xffffffffu, v1, 1);
                    float r2 = __shfl_xor_sync(0xffffffffu, v2, 1);
                    float r3 = __shfl_xor_sync(0xffffffffu, v3, 1);
                    int c4 = ch*32 + n*8 + 4*(tig >> 1);
                    if ((tig & 1) == 0) {
                        if (dA < NN)
                            red_add_v4(g_agg + (size_t)dA*64 + c4, v0, v1, r0, r1);
                    } else {
                        if (dB < NN)
                            red_add_v4(g_agg + (size_t)dB*64 + c4, r2, r3, v2, v3);
                    }
                }
            }
        }
    }
}

// ---------------- GRU via bf16 MMA: gates = [agg|h] @ W'; writes g_h and g_hb ----------------
#define PMI2 136
#define GRUM_WF   34816
#define GRUM_B    83968
#define GRUM_SMEM 84992
#define GRU_NT    ((NN + 127) / 128)

__global__ __launch_bounds__(ETPB, 2) void tg_gruM(const float* __restrict__ wi,
    const float* __restrict__ wh, const float* __restrict__ bi, const float* __restrict__ bh)
{
    extern __shared__ char smraw[];
    uint32_t* sWF = (uint32_t*)(smraw + GRUM_WF);
    float* sbr  = (float*)(smraw + GRUM_B);
    float* sbz  = sbr + 64;
    float* sbin = sbr + 128;
    float* sbhn = sbr + 192;

    int tid = threadIdx.x, lane = tid & 31, warp = tid >> 5;
    int grp = lane >> 2, tig = lane & 3;

    // stage fragment-major W' once
    for (int i = tid; i < 12288; i += ETPB) {
        int w = i & 1, ln = (i >> 1) & 31, slot = i >> 6;
        int g = ln >> 2, tg = ln & 3;
        int kk = 2*tg + 8*w;
        float v0, v1;
        if (slot < 128) {
            int kb = slot & 7, nc = slot >> 3;
            int cc = (nc & 7)*8 + g + ((nc >> 3) << 6);   // r: 0-63, z: 64-127
            int k = kb*16 + kk;
            const float* s = (k < 64) ? (wi + k*192 + cc) : (wh + (k-64)*192 + cc);
            v0 = s[0]; v1 = s[192];
        } else if (slot < 160) {
            int s2 = slot - 128; int kb = s2 & 3, nc = s2 >> 2;
            const float* s = wi + (kb*16 + kk)*192 + nc*8 + g + 128;
            v0 = s[0]; v1 = s[192];
        } else {
            int s2 = slot - 160; int kb = s2 & 3, nc = s2 >> 2;
            const float* s = wh + (kb*16 + kk)*192 + nc*8 + g + 128;
            v0 = s[0]; v1 = s[192];
        }
        sWF[i] = bf2(v0, v1);
    }
    if (tid < 64) {
        sbr[tid]  = bi[tid]       + bh[tid];
        sbz[tid]  = bi[64 + tid]  + bh[64 + tid];
        sbin[tid] = bi[128 + tid];
        sbhn[tid] = bh[128 + tid];
    }

    uint32_t aBase = smem_u32(smraw);

    for (int tile = blockIdx.x; tile < GRU_NT; tile += gridDim.x) {
        int nbase = tile * 128;
        __syncthreads();   // previous tile's MMA reads done before overwriting A
        // gather [agg | h(bf16 mirror)] -> bf16 A tile; zero g_agg as we consume it
        for (int i = tid; i < 4096; i += ETPB) {
            int ee = i >> 5, c = i & 31;
            int node = nbase + ee;
            uint2 u;
            if (node < NN) {
                if (c < 16) {
                    float4 v = ((const float4*)(g_agg + (size_t)node*64))[c];
                    u.x = bf2(v.x, v.y); u.y = bf2(v.z, v.w);
                    ((float4*)(g_agg + (size_t)node*64))[c] = make_float4(0.f, 0.f, 0.f, 0.f);
                } else {
                    u = *(const uint2*)(g_hb + (size_t)node*64 + (c & 15)*4);
                }
            } else { u.x = 0u; u.y = 0u; }
            *(uint2*)(smraw + ee*(PMI2*2) + c*8) = u;
        }
        __syncthreads();

        for (int task = warp; task < 32; task += 16) {
            int eg = task & 7, cq = task >> 3;
            uint32_t aAddr = aBase + (eg*16 + (lane & 15))*(PMI2*2) + (lane >> 4)*16;
            #pragma unroll
            for (int n = 0; n < 2; n++) {
                int ncq = cq*2 + n;
                float acc[4][4];
                #pragma unroll
                for (int q = 0; q < 4; q++) { acc[q][0]=0.f; acc[q][1]=0.f; acc[q][2]=0.f; acc[q][3]=0.f; }
                #pragma unroll
                for (int kb = 0; kb < 8; kb++) {
                    uint32_t a0, a1, a2, a3;
                    ldsm4(a0, a1, a2, a3, aAddr + kb*32);
                    uint2 bv;
                    bv = *(const uint2*)(sWF + ((ncq*8 + kb) << 6) + 2*lane);          // r
                    mma_bf16(acc[0], a0, a1, a2, a3, bv.x, bv.y);
                    bv = *(const uint2*)(sWF + (((8 + ncq)*8 + kb) << 6) + 2*lane);    // z
                    mma_bf16(acc[1], a0, a1, a2, a3, bv.x, bv.y);
                    if (kb < 4) {
                        bv = *(const uint2*)(sWF + ((128 + ncq*4 + kb) << 6) + 2*lane);   // i_n
                        mma_bf16(acc[2], a0, a1, a2, a3, bv.x, bv.y);
                    } else {
                        bv = *(const uint2*)(sWF + ((160 + ncq*4 + kb - 4) << 6) + 2*lane); // h_n
                        mma_bf16(acc[3], a0, a1, a2, a3, bv.x, bv.y);
                    }
                }
                int c0 = cq*16 + n*8 + 2*tig;
                float2 br2  = *(const float2*)(sbr  + c0);
                float2 bz2  = *(const float2*)(sbz  + c0);
                float2 bin2 = *(const float2*)(sbin + c0);
                float2 bhn2 = *(const float2*)(sbhn + c0);
                #pragma unroll
                for (int half = 0; half < 2; half++) {
                    int node = nbase + eg*16 + grp + half*8;
                    if (node < NN) {
                        int q = half*2;
                        float* hp = g_h + (size_t)node*64 + c0;
                        float2 hold = *(float2*)hp;
                        float r0 = sigf(acc[0][q]   + br2.x);
                        float r1 = sigf(acc[0][q+1] + br2.y);
                        float z0 = sigf(acc[1][q]   + bz2.x);
                        float z1 = sigf(acc[1][q+1] + bz2.y);
                        float nn0 = tanhf(acc[2][q]   + bin2.x + r0*(acc[3][q]   + bhn2.x));
                        float nn1 = tanhf(acc[2][q+1] + bin2.y + r1*(acc[3][q+1] + bhn2.y));
                        float2 o;
                        o.x = (1.f - z0)*nn0 + z0*hold.x;
                        o.y = (1.f - z1)*nn1 + z1*hold.y;
                        *(float2*)hp = o;
                        *(uint32_t*)(g_hb + (size_t)node*64 + c0) = bf2(o.x, o.y);
                    }
                }
            }
        }
    }
}

// ---------------- readout + correction ----------------
__global__ __launch_bounds__(TPB) void tg_readout(const float* __restrict__ x,
    const int* __restrict__ ntype, const float* __restrict__ w1, const float* __restrict__ b1,
    const float* __restrict__ w2, const float* __restrict__ b2, float* __restrict__ out)
{
    __shared__ float sw[4096], sv[64], sb[64];
    for (int i = threadIdx.x; i < 4096; i += TPB) sw[i] = w1[i];
    if (threadIdx.x < 64) { sv[threadIdx.x] = w2[threadIdx.x]; sb[threadIdx.x] = b1[threadIdx.x]; }
    __syncthreads();
    int lane = threadIdx.x & 31;
    int warpsTotal = gridDim.x * (TPB/32);
    for (int node = blockIdx.x*(TPB/32) + (threadIdx.x>>5); node < NN; node += warpsTotal) {
        const float* hp = g_h + (size_t)node*64;
        float h0 = hp[lane], h1 = hp[lane+32];
        float acc0 = 0.f, acc1 = 0.f;
        #pragma unroll
        for (int k = 0; k < 32; k++) {
            float hk = __shfl_sync(0xffffffffu, h0, k);
            acc0 = fmaf(hk, sw[k*64+lane],    acc0);
            acc1 = fmaf(hk, sw[k*64+lane+32], acc1);
        }
        #pragma unroll
        for (int k = 0; k < 32; k++) {
            float hk = __shfl_sync(0xffffffffu, h1, k);
            acc0 = fmaf(hk, sw[(k+32)*64+lane],    acc0);
            acc1 = fmaf(hk, sw[(k+32)*64+lane+32], acc1);
        }
        float t0 = fmaxf(acc0 + sb[lane],    0.f);
        float t1 = fmaxf(acc1 + sb[lane+32], 0.f);
        float p = t0*sv[lane] + t1*sv[lane+32];
        #pragma unroll
        for (int o = 16; o; o >>= 1) p += __shfl_xor_sync(0xffffffffu, p, o);
        if (lane == 0)
            out[node] = (ntype[node] == 0) ? (x[node*4] + p + b2[0]) : 0.f;
    }
}

// ---------------- launch ----------------
extern "C" void kernel_launch(void* const* d_in, const int* in_sizes, int n_in,
                              void* d_out, int out_size)
{
    const float* x        = (const float*)d_in[0];
    const int*   ntype    = (const int*)  d_in[1];
    const int*   eindex   = (const int*)  d_in[2];
    const int*   etype    = (const int*)  d_in[3];
    const float* in_w     = (const float*)d_in[4];
    const float* in_b     = (const float*)d_in[5];
    const float* ln_g     = (const float*)d_in[6];
    const float* ln_b     = (const float*)d_in[7];
    const float* mlp_w1   = (const float*)d_in[8];
    const float* mlp_b1   = (const float*)d_in[9];
    const float* mlp_w2   = (const float*)d_in[10];
    const float* mlp_b2   = (const float*)d_in[11];
    const float* gru_wi   = (const float*)d_in[12];
    const float* gru_wh   = (const float*)d_in[13];
    const float* gru_bi   = (const float*)d_in[14];
    const float* gru_bh   = (const float*)d_in[15];
    const float* ro_w1    = (const float*)d_in[16];
    const float* ro_b1    = (const float*)d_in[17];
    const float* ro_w2    = (const float*)d_in[18];
    const float* ro_b2    = (const float*)d_in[19];
    float* out = (float*)d_out;

    cudaFuncSetAttribute(tg_edge, cudaFuncAttributeMaxDynamicSharedMemorySize, EDGE_SMEM);
    cudaFuncSetAttribute(tg_gruM, cudaFuncAttributeMaxDynamicSharedMemorySize, GRUM_SMEM);

    tg_countscan<<<512, TPB>>>(etype);
    tg_scatter<<<512, TPB>>>(etype, eindex);
    tg_input<<<304, TPB>>>(x, in_w, in_b, ln_g, ln_b);

    for (int l = 0; l < 3; l++) {
        tg_edge<<<148, ETPB, EDGE_SMEM>>>(mlp_w1 + l*2*8192, mlp_b1 + l*2*64,
                                          mlp_w2 + l*2*4096, mlp_b2 + l*2*64);
        tg_gruM<<<296, ETPB, GRUM_SMEM>>>(gru_wi + l*12288, gru_wh + l*12288,
                                          gru_bi + l*192,   gru_bh + l*192);
    }
    tg_readout<<<304, TPB>>>(x, ntype, ro_w1, ro_b1, ro_w2, ro_b2, out);
}